// round 13
// baseline (speedup 1.0000x reference)
#include <cuda_runtime.h>
#include <cuda_fp16.h>
#include <math.h>
#include <stdint.h>

// ---------------------------------------------------------------------------
// ImbalancedGAT R13: agg1 gathers widened to uint4 (16B/lane; 8 lanes/edge,
// 4 edges per LDG.128) -> half the load+addr instructions in the binding
// loop. Fixed-slot CSR, stream-fork, single-stage TC GEMM retained.
// ---------------------------------------------------------------------------

#define MAXN 65536
#define SLOTS 128

__device__ __half  g_xw1h[MAXN * 128]; // layer1 transformed features (fp16)
__device__ float   g_as1[MAXN * 2];    // alpha_src layer1 (per head)
__device__ float   g_ad1[MAXN * 2];    // alpha_dst layer1
__device__ float4  g_n2[MAXN];         // {xw2_0, xw2_1, as2, ad2}
__device__ int     g_cnt[MAXN];        // row length (starts at 1: self loop)
__device__ int     g_colf[MAXN * SLOTS]; // fixed-slot adjacency
__device__ int     g_is64;

__device__ __forceinline__ float lrelu(float x) { return x > 0.f ? x : 0.2f * x; }
__device__ __forceinline__ float elu(float x)   { return x > 0.f ? x : (expf(x) - 1.f); }

// ---- init: cnt=1, self loop at slot 0, dtype detection --------------------
__global__ void init_kernel(const unsigned int* ew, int n) {
    int i = blockIdx.x * blockDim.x + threadIdx.x;
    if (i < n) {
        g_cnt[i] = 1;
        g_colf[i << 7] = i;   // self loop at row head
    }
    if (blockIdx.x == 0 && threadIdx.x < 32) {
        int lane = threadIdx.x;
        int nz = 0;
        for (int k = lane; k < 1024; k += 32) nz += (ew[2 * k + 1] != 0u);
        for (int o = 16; o; o >>= 1) nz += __shfl_xor_sync(0xffffffffu, nz, o);
        if (lane == 0) g_is64 = (nz == 0);  // all-zero high words => int64
    }
}

// ---- fill: 4 edges/thread, independent atomic chains ----------------------
__global__ void fill_kernel(const void* e, int E) {
    int t = blockIdx.x * blockDim.x + threadIdx.x;
    int base = t * 4;
    if (base >= E) return;
    int n = E - base; if (n > 4) n = 4;
    int s[4], d[4];
    if (g_is64) {
        const long long* ps = (const long long*)e + base;
        const long long* pd = (const long long*)e + E + base;
        if (n == 4) {
            longlong2 a = *(const longlong2*)ps, b = *(const longlong2*)(ps + 2);
            longlong2 c = *(const longlong2*)pd, f = *(const longlong2*)(pd + 2);
            s[0]=(int)a.x; s[1]=(int)a.y; s[2]=(int)b.x; s[3]=(int)b.y;
            d[0]=(int)c.x; d[1]=(int)c.y; d[2]=(int)f.x; d[3]=(int)f.y;
        } else {
            for (int i = 0; i < n; i++) { s[i]=(int)ps[i]; d[i]=(int)pd[i]; }
        }
    } else {
        const int* ps = (const int*)e + base;
        const int* pd = (const int*)e + E + base;
        if (n == 4) {
            int4 sv = *(const int4*)ps, dv = *(const int4*)pd;
            s[0]=sv.x; s[1]=sv.y; s[2]=sv.z; s[3]=sv.w;
            d[0]=dv.x; d[1]=dv.y; d[2]=dv.z; d[3]=dv.w;
        } else {
            for (int i = 0; i < n; i++) { s[i]=ps[i]; d[i]=pd[i]; }
        }
    }
#pragma unroll
    for (int i = 0; i < 4; i++) {
        if (i < n) {
            int pos = atomicAdd(&g_cnt[d[i]], 1);
            if (pos < SLOTS) g_colf[(d[i] << 7) + pos] = s[i];
        }
    }
}

// ---- mma helpers ----------------------------------------------------------
__device__ __forceinline__ void ldsm_x4(uint32_t addr, uint32_t* r) {
    asm volatile("ldmatrix.sync.aligned.m8n8.x4.shared.b16 {%0,%1,%2,%3}, [%4];"
                 : "=r"(r[0]), "=r"(r[1]), "=r"(r[2]), "=r"(r[3]) : "r"(addr));
}
__device__ __forceinline__ void ldsm_x4_t(uint32_t addr, uint32_t* r) {
    asm volatile("ldmatrix.sync.aligned.m8n8.x4.trans.shared.b16 {%0,%1,%2,%3}, [%4];"
                 : "=r"(r[0]), "=r"(r[1]), "=r"(r[2]), "=r"(r[3]) : "r"(addr));
}
__device__ __forceinline__ void mma16816(float* c, const uint32_t* a, const uint32_t* b) {
    asm volatile("mma.sync.aligned.m16n8k16.row.col.f32.f16.f16.f32 "
                 "{%0,%1,%2,%3}, {%4,%5,%6,%7}, {%8,%9}, {%0,%1,%2,%3};"
                 : "+f"(c[0]), "+f"(c[1]), "+f"(c[2]), "+f"(c[3])
                 : "r"(a[0]), "r"(a[1]), "r"(a[2]), "r"(a[3]), "r"(b[0]), "r"(b[1]));
}

// ---- GEMM1 + alpha1 fused: single K=128 stage, dynamic smem ---------------
#define TS 136                                // half stride (17x16B: odd granule)
#define GSM_BYTES (2 * 128 * TS * 2)          // xs + ws = 69632

__global__ void __launch_bounds__(256) gemm1a_kernel(
        const float* __restrict__ x, const float* __restrict__ W,
        const float* __restrict__ a_src, const float* __restrict__ a_dst, int N) {
    extern __shared__ __align__(16) unsigned char smbuf[];
    __half* xs = (__half*)smbuf;                    // [128][TS]
    __half* ws = (__half*)(smbuf + 128 * TS * 2);   // [128][TS]

    int tid  = threadIdx.x;
    int lane = tid & 31;
    int wid  = tid >> 5;
    int row0 = blockIdx.x * 128;
    int R0 = (wid >> 1) * 32;      // warp row base
    int C0 = (wid & 1) * 64;       // warp col base (== head * 64)

#pragma unroll
    for (int j = 0; j < 16; j++) {
        int i = tid + j * 256;
        int r = i >> 5, fc = i & 31;
        int gr = row0 + r; if (gr >= N) gr = N - 1;
        float4 v = *(const float4*)&x[(size_t)gr * 128 + fc * 4];
        __half2* dst = (__half2*)&xs[r * TS + fc * 4];
        dst[0] = __floats2half2_rn(v.x, v.y);
        dst[1] = __floats2half2_rn(v.z, v.w);
    }
#pragma unroll
    for (int j = 0; j < 16; j++) {
        int i = tid + j * 256;
        int r = i >> 5, fc = i & 31;
        float4 v = *(const float4*)&W[(size_t)r * 128 + fc * 4];
        __half2* dst = (__half2*)&ws[r * TS + fc * 4];
        dst[0] = __floats2half2_rn(v.x, v.y);
        dst[1] = __floats2half2_rn(v.z, v.w);
    }
    __syncthreads();

    float acc[2][8][4];
#pragma unroll
    for (int mt = 0; mt < 2; mt++)
#pragma unroll
        for (int nt = 0; nt < 8; nt++)
#pragma unroll
            for (int c = 0; c < 4; c++) acc[mt][nt][c] = 0.f;

    uint32_t xs_base = (uint32_t)__cvta_generic_to_shared(xs);
    uint32_t ws_base = (uint32_t)__cvta_generic_to_shared(ws);

#pragma unroll
    for (int kt = 0; kt < 8; kt++) {
        uint32_t af[2][4];
#pragma unroll
        for (int mt = 0; mt < 2; mt++) {
            uint32_t addr = xs_base + 2 * ((R0 + mt * 16 + (lane & 15)) * TS
                                           + kt * 16 + (lane >> 4) * 8);
            ldsm_x4(addr, af[mt]);
        }
        uint32_t bf[4][4];
#pragma unroll
        for (int np = 0; np < 4; np++) {
            uint32_t addr = ws_base + 2 * ((kt * 16 + (lane & 15)) * TS
                                           + C0 + np * 16 + (lane >> 4) * 8);
            ldsm_x4_t(addr, bf[np]);
        }
#pragma unroll
        for (int mt = 0; mt < 2; mt++)
#pragma unroll
            for (int np = 0; np < 4; np++) {
                mma16816(acc[mt][2 * np],     af[mt], &bf[np][0]);
                mma16816(acc[mt][2 * np + 1], af[mt], &bf[np][2]);
            }
    }

    // ---- alpha epilogue (fp32 from accumulators) ----
    float2 as_l[8], ad_l[8];
#pragma unroll
    for (int nt = 0; nt < 8; nt++) {
        int col = C0 + nt * 8 + (lane & 3) * 2;
        as_l[nt] = *(const float2*)&a_src[col];
        ad_l[nt] = *(const float2*)&a_dst[col];
    }
    int head = wid & 1;
#pragma unroll
    for (int mt = 0; mt < 2; mt++)
#pragma unroll
        for (int rh = 0; rh < 2; rh++) {
            float ps = 0.f, pd = 0.f;
#pragma unroll
            for (int nt = 0; nt < 8; nt++) {
                float v0 = acc[mt][nt][2 * rh], v1 = acc[mt][nt][2 * rh + 1];
                ps += v0 * as_l[nt].x + v1 * as_l[nt].y;
                pd += v0 * ad_l[nt].x + v1 * ad_l[nt].y;
            }
            ps += __shfl_xor_sync(0xffffffffu, ps, 1);
            pd += __shfl_xor_sync(0xffffffffu, pd, 1);
            ps += __shfl_xor_sync(0xffffffffu, ps, 2);
            pd += __shfl_xor_sync(0xffffffffu, pd, 2);
            if ((lane & 3) == 0) {
                int row = row0 + R0 + mt * 16 + rh * 8 + (lane >> 2);
                if (row < N) {
                    g_as1[2 * row + head] = ps;
                    g_ad1[2 * row + head] = pd;
                }
            }
        }

    // ---- direct fp16 stores ----
#pragma unroll
    for (int mt = 0; mt < 2; mt++)
#pragma unroll
        for (int nt = 0; nt < 8; nt++) {
            int r  = row0 + R0 + mt * 16 + (lane >> 2);
            int cc = C0 + nt * 8 + (lane & 3) * 2;
            if (r < N)
                *(__half2*)&g_xw1h[(size_t)r * 128 + cc] =
                    __floats2half2_rn(acc[mt][nt][0], acc[mt][nt][1]);
            if (r + 8 < N)
                *(__half2*)&g_xw1h[(size_t)(r + 8) * 128 + cc] =
                    __floats2half2_rn(acc[mt][nt][2], acc[mt][nt][3]);
        }
}

// ---- Layer1 aggregation: 2 warps/node, uint4 gathers ----------------------
// 8 lanes cover one edge's 64-ch head half (16B/lane); 4 edges per LDG.128.
// c8 = lane&7 -> channel octet, grp = lane>>3 -> edge slot within quad.
__global__ void __launch_bounds__(256) agg1_kernel(
        const float* __restrict__ b1, const float* __restrict__ W2,
        const float* __restrict__ a_src2, const float* __restrict__ a_dst2, int N) {
    __shared__ int   s_sh[8][64];
    __shared__ float w_sh[8][64];
    __shared__ float p_sh[8][2];
    int wip  = threadIdx.x >> 5;
    int lane = threadIdx.x & 31;
    int d    = blockIdx.x * 4 + (wip >> 1);
    int head = wip & 1;
    bool valid = d < N;

    if (valid) {
        int rbase = d << 7;
        int cntr  = g_cnt[d]; if (cntr > SLOTS) cntr = SLOTS;
        float adv = g_ad1[2 * d + head];
        int c8  = lane & 7;       // channel octet (8 ch)
        int grp = lane >> 3;      // edge slot 0..3
        const __half* bx = g_xw1h + head * 64 + c8 * 8;
        float4 aA0 = make_float4(0.f,0.f,0.f,0.f), aA1 = make_float4(0.f,0.f,0.f,0.f);
        float4 aB0 = make_float4(0.f,0.f,0.f,0.f), aB1 = make_float4(0.f,0.f,0.f,0.f);
        float ds = 0.f;
        int*   ss = s_sh[wip];
        float* ws = w_sh[wip];

        for (int b0 = 0; b0 < cntr; b0 += 64) {
            int i0 = b0 + lane, i1 = b0 + 32 + lane;
            int s0 = d, s1 = d; float w0 = 0.f, w1 = 0.f;
            if (i0 < cntr) {
                s0 = g_colf[rbase + i0];
                w0 = __expf(lrelu(g_as1[2 * s0 + head] + adv));  // no max: bounded
                ds += w0;
            }
            if (i1 < cntr) {
                s1 = g_colf[rbase + i1];
                w1 = __expf(lrelu(g_as1[2 * s1 + head] + adv));
                ds += w1;
            }
            __syncwarp();
            ss[lane] = s0; ws[lane] = w0;
            ss[32 + lane] = s1; ws[32 + lane] = w1;
            __syncwarp();
            int cnt = cntr - b0; if (cnt > 64) cnt = 64;
            cnt = (cnt + 7) & ~7;                  // pad: w=0 entries no-op
            for (int g = 0; g < cnt; g += 8) {
                int   sA = ss[g + grp];
                int   sB = ss[g + 4 + grp];
                float wA = ws[g + grp];
                float wB = ws[g + 4 + grp];
                uint4 rA = *(const uint4*)&bx[(size_t)sA * 128];
                uint4 rB = *(const uint4*)&bx[(size_t)sB * 128];
                float2 a0 = __half22float2(*(__half2*)&rA.x);
                float2 a1 = __half22float2(*(__half2*)&rA.y);
                float2 a2 = __half22float2(*(__half2*)&rA.z);
                float2 a3 = __half22float2(*(__half2*)&rA.w);
                float2 b0f = __half22float2(*(__half2*)&rB.x);
                float2 b1f = __half22float2(*(__half2*)&rB.y);
                float2 b2f = __half22float2(*(__half2*)&rB.z);
                float2 b3f = __half22float2(*(__half2*)&rB.w);
                aA0.x += wA * a0.x; aA0.y += wA * a0.y;
                aA0.z += wA * a1.x; aA0.w += wA * a1.y;
                aA1.x += wA * a2.x; aA1.y += wA * a2.y;
                aA1.z += wA * a3.x; aA1.w += wA * a3.y;
                aB0.x += wB * b0f.x; aB0.y += wB * b0f.y;
                aB0.z += wB * b1f.x; aB0.w += wB * b1f.y;
                aB1.x += wB * b2f.x; aB1.y += wB * b2f.y;
                aB1.z += wB * b3f.x; aB1.w += wB * b3f.y;
            }
        }
        // merge A/B chains, then reduce across the 4 edge-slot groups
        aA0.x += aB0.x; aA0.y += aB0.y; aA0.z += aB0.z; aA0.w += aB0.w;
        aA1.x += aB1.x; aA1.y += aB1.y; aA1.z += aB1.z; aA1.w += aB1.w;
#pragma unroll
        for (int o = 8; o <= 16; o <<= 1) {
            aA0.x += __shfl_xor_sync(0xffffffffu, aA0.x, o);
            aA0.y += __shfl_xor_sync(0xffffffffu, aA0.y, o);
            aA0.z += __shfl_xor_sync(0xffffffffu, aA0.z, o);
            aA0.w += __shfl_xor_sync(0xffffffffu, aA0.w, o);
            aA1.x += __shfl_xor_sync(0xffffffffu, aA1.x, o);
            aA1.y += __shfl_xor_sync(0xffffffffu, aA1.y, o);
            aA1.z += __shfl_xor_sync(0xffffffffu, aA1.z, o);
            aA1.w += __shfl_xor_sync(0xffffffffu, aA1.w, o);
        }
#pragma unroll
        for (int o = 16; o; o >>= 1)
            ds += __shfl_xor_sync(0xffffffffu, ds, o);
        float inv = 1.f / (ds + 1e-16f);
        int cg = head * 64 + c8 * 8;
        float4 bb0 = *(const float4*)&b1[cg];
        float4 bb1 = *(const float4*)&b1[cg + 4];
        float h0 = elu(aA0.x * inv + bb0.x);
        float h1 = elu(aA0.y * inv + bb0.y);
        float h2 = elu(aA0.z * inv + bb0.z);
        float h3 = elu(aA0.w * inv + bb0.w);
        float h4 = elu(aA1.x * inv + bb1.x);
        float h5 = elu(aA1.y * inv + bb1.y);
        float h6 = elu(aA1.z * inv + bb1.z);
        float h7 = elu(aA1.w * inv + bb1.w);
        // fused layer2 transform partials over this lane's 8 channels
        float p0 = h0*W2[2*cg]     + h1*W2[2*(cg+1)]   + h2*W2[2*(cg+2)]   + h3*W2[2*(cg+3)]
                 + h4*W2[2*(cg+4)] + h5*W2[2*(cg+5)]   + h6*W2[2*(cg+6)]   + h7*W2[2*(cg+7)];
        float p1 = h0*W2[2*cg+1]     + h1*W2[2*(cg+1)+1] + h2*W2[2*(cg+2)+1] + h3*W2[2*(cg+3)+1]
                 + h4*W2[2*(cg+4)+1] + h5*W2[2*(cg+5)+1] + h6*W2[2*(cg+6)+1] + h7*W2[2*(cg+7)+1];
#pragma unroll
        for (int o = 1; o < 8; o <<= 1) {      // reduce across the 8 c8 lanes
            p0 += __shfl_xor_sync(0xffffffffu, p0, o);
            p1 += __shfl_xor_sync(0xffffffffu, p1, o);
        }
        if (lane == 0) { p_sh[wip][0] = p0; p_sh[wip][1] = p1; }
    }
    __syncthreads();
    if (valid && head == 0 && lane == 0) {
        float q0 = p_sh[wip][0] + p_sh[wip + 1][0];
        float q1 = p_sh[wip][1] + p_sh[wip + 1][1];
        float4 nv;
        nv.x = q0; nv.y = q1;
        nv.z = q0 * a_src2[0] + q1 * a_src2[1];
        nv.w = q0 * a_dst2[0] + q1 * a_dst2[1];
        g_n2[d] = nv;
    }
}

// ---- Layer2 aggregation: warp per dst node, single pass -------------------
__global__ void agg2_kernel(const float* __restrict__ b2, float* __restrict__ out, int N) {
    int warp = (blockIdx.x * blockDim.x + threadIdx.x) >> 5;
    int lane = threadIdx.x & 31;
    if (warp >= N) return;
    int d = warp;
    int rbase = d << 7;
    int cntr  = g_cnt[d]; if (cntr > SLOTS) cntr = SLOTS;
    float adv = g_n2[d].w;
    float a0 = 0.f, a1 = 0.f, ds = 0.f;
    for (int i = lane; i < cntr; i += 32) {
        float4 nv = g_n2[g_colf[rbase + i]];
        float w = __expf(lrelu(nv.z + adv));
        ds += w; a0 += w * nv.x; a1 += w * nv.y;
    }
#pragma unroll
    for (int o = 16; o; o >>= 1) {
        a0 += __shfl_xor_sync(0xffffffffu, a0, o);
        a1 += __shfl_xor_sync(0xffffffffu, a1, o);
        ds += __shfl_xor_sync(0xffffffffu, ds, o);
    }
    if (lane == 0) {
        float inv = 1.f / (ds + 1e-16f);
        out[2 * d]     = a0 * inv + b2[0];
        out[2 * d + 1] = a1 * inv + b2[1];
    }
}

// ---------------------------------------------------------------------------
extern "C" void kernel_launch(void* const* d_in, const int* in_sizes, int n_in,
                              void* d_out, int out_size) {
    const float* x    = (const float*)d_in[0];
    const void*  eidx = d_in[1];
    const float* W1   = (const float*)d_in[2];
    const float* as1  = (const float*)d_in[3];
    const float* ad1  = (const float*)d_in[4];
    const float* b1   = (const float*)d_in[5];
    const float* W2   = (const float*)d_in[6];
    const float* as2  = (const float*)d_in[7];
    const float* ad2  = (const float*)d_in[8];
    const float* b2   = (const float*)d_in[9];

    int N = in_sizes[0] / 128;
    int E = in_sizes[1] / 2;
    int nt4 = (E + 3) / 4;

    static cudaStream_t s_side = nullptr;
    static cudaEvent_t  ev_fork = nullptr, ev_join = nullptr;
    if (!s_side) {   // created on the uncaptured correctness call, reused after
        cudaStreamCreateWithFlags(&s_side, cudaStreamNonBlocking);
        cudaEventCreateWithFlags(&ev_fork, cudaEventDisableTiming);
        cudaEventCreateWithFlags(&ev_join, cudaEventDisableTiming);
        cudaFuncSetAttribute(gemm1a_kernel,
                             cudaFuncAttributeMaxDynamicSharedMemorySize, GSM_BYTES);
    }

    // main: init, then fork fill to side stream; GEMM overlaps it.
    init_kernel<<<(N + 255) / 256, 256>>>((const unsigned int*)eidx, N);   // 0
    cudaEventRecord(ev_fork, 0);
    cudaStreamWaitEvent(s_side, ev_fork, 0);

    fill_kernel<<<(nt4 + 255) / 256, 256, 0, s_side>>>(eidx, E);           // 1
    cudaEventRecord(ev_join, s_side);

    gemm1a_kernel<<<(N + 127) / 128, 256, GSM_BYTES>>>(x, W1, as1, ad1, N);// 2

    cudaStreamWaitEvent(0, ev_join, 0);
    agg1_kernel<<<(N + 3) / 4, 256>>>(b1, W2, as2, ad2, N);                // 3 <- profiled
    agg2_kernel<<<(N + 7) / 8, 256>>>(b2, (float*)d_out, N);               // 4
}

// round 14
// speedup vs baseline: 1.0013x; 1.0013x over previous
#include <cuda_runtime.h>
#include <cuda_fp16.h>
#include <math.h>
#include <stdint.h>

// ---------------------------------------------------------------------------
// ImbalancedGAT R14: R12's proven agg1 gather pattern restored; edge weights
// precomputed by an edge-parallel wgt kernel (zero-padded to 8-slot boundary,
// padding colf sanitized) -> agg1 loses weight-compute, staging smem,
// syncwarps, and the ds shuffle reduction. Fixed-slot CSR, stream-fork,
// single-stage TC GEMM retained.
// ---------------------------------------------------------------------------

#define MAXN 65536
#define SLOTS 128

__device__ __half  g_xw1h[MAXN * 128]; // layer1 transformed features (fp16)
__device__ float   g_as1[MAXN * 2];    // alpha_src layer1 (per head)
__device__ float   g_ad1[MAXN * 2];    // alpha_dst layer1
__device__ float4  g_n2[MAXN];         // {xw2_0, xw2_1, as2, ad2}
__device__ int     g_cnt[MAXN];        // row length (starts at 1: self loop)
__device__ int     g_colf[MAXN * SLOTS]; // fixed-slot adjacency
__device__ float   g_w0[MAXN * SLOTS]; // per-edge softmax weights head0
__device__ float   g_w1[MAXN * SLOTS]; // per-edge softmax weights head1
__device__ int     g_is64;

__device__ __forceinline__ float lrelu(float x) { return x > 0.f ? x : 0.2f * x; }
__device__ __forceinline__ float elu(float x)   { return x > 0.f ? x : (expf(x) - 1.f); }

// ---- init: cnt=1, self loop at slot 0, dtype detection --------------------
__global__ void init_kernel(const unsigned int* ew, int n) {
    int i = blockIdx.x * blockDim.x + threadIdx.x;
    if (i < n) {
        g_cnt[i] = 1;
        g_colf[i << 7] = i;   // self loop at row head
    }
    if (blockIdx.x == 0 && threadIdx.x < 32) {
        int lane = threadIdx.x;
        int nz = 0;
        for (int k = lane; k < 1024; k += 32) nz += (ew[2 * k + 1] != 0u);
        for (int o = 16; o; o >>= 1) nz += __shfl_xor_sync(0xffffffffu, nz, o);
        if (lane == 0) g_is64 = (nz == 0);  // all-zero high words => int64
    }
}

// ---- fill: 4 edges/thread, independent atomic chains ----------------------
__global__ void fill_kernel(const void* e, int E) {
    int t = blockIdx.x * blockDim.x + threadIdx.x;
    int base = t * 4;
    if (base >= E) return;
    int n = E - base; if (n > 4) n = 4;
    int s[4], d[4];
    if (g_is64) {
        const long long* ps = (const long long*)e + base;
        const long long* pd = (const long long*)e + E + base;
        if (n == 4) {
            longlong2 a = *(const longlong2*)ps, b = *(const longlong2*)(ps + 2);
            longlong2 c = *(const longlong2*)pd, f = *(const longlong2*)(pd + 2);
            s[0]=(int)a.x; s[1]=(int)a.y; s[2]=(int)b.x; s[3]=(int)b.y;
            d[0]=(int)c.x; d[1]=(int)c.y; d[2]=(int)f.x; d[3]=(int)f.y;
        } else {
            for (int i = 0; i < n; i++) { s[i]=(int)ps[i]; d[i]=(int)pd[i]; }
        }
    } else {
        const int* ps = (const int*)e + base;
        const int* pd = (const int*)e + E + base;
        if (n == 4) {
            int4 sv = *(const int4*)ps, dv = *(const int4*)pd;
            s[0]=sv.x; s[1]=sv.y; s[2]=sv.z; s[3]=sv.w;
            d[0]=dv.x; d[1]=dv.y; d[2]=dv.z; d[3]=dv.w;
        } else {
            for (int i = 0; i < n; i++) { s[i]=ps[i]; d[i]=pd[i]; }
        }
    }
#pragma unroll
    for (int i = 0; i < 4; i++) {
        if (i < n) {
            int pos = atomicAdd(&g_cnt[d[i]], 1);
            if (pos < SLOTS) g_colf[(d[i] << 7) + pos] = s[i];
        }
    }
}

// ---- wgt: edge-parallel weight precompute (quad of slots per thread) ------
// Zero-pads weights up to the 8-slot boundary and sanitizes padding colf
// entries so agg1's gathers are always in-bounds.
__global__ void wgt_kernel(int N) {
    int t = blockIdx.x * blockDim.x + threadIdx.x;
    int d = t >> 5, q = t & 31;
    if (d >= N) return;
    int cnt = g_cnt[d]; if (cnt > SLOTS) cnt = SLOTS;
    int pad = (cnt + 7) & ~7;
    int s0 = q << 2;
    if (s0 >= pad) return;
    int base = (d << 7) + s0;
    float ad0 = g_ad1[2 * d], ad1v = g_ad1[2 * d + 1];
    int4 s4 = *(const int4*)&g_colf[base];
    int sarr[4] = { s4.x, s4.y, s4.z, s4.w };
    float w0[4], w1[4];
    bool dirty = false;
#pragma unroll
    for (int i = 0; i < 4; i++) {
        if (s0 + i < cnt) {
            float2 a = *(const float2*)&g_as1[2 * sarr[i]];
            w0[i] = __expf(lrelu(a.x + ad0));   // no max: logits bounded
            w1[i] = __expf(lrelu(a.y + ad1v));
        } else {
            w0[i] = 0.f; w1[i] = 0.f; sarr[i] = d; dirty = true;
        }
    }
    *(float4*)&g_w0[base] = make_float4(w0[0], w0[1], w0[2], w0[3]);
    *(float4*)&g_w1[base] = make_float4(w1[0], w1[1], w1[2], w1[3]);
    if (dirty)
        *(int4*)&g_colf[base] = make_int4(sarr[0], sarr[1], sarr[2], sarr[3]);
}

// ---- mma helpers ----------------------------------------------------------
__device__ __forceinline__ void ldsm_x4(uint32_t addr, uint32_t* r) {
    asm volatile("ldmatrix.sync.aligned.m8n8.x4.shared.b16 {%0,%1,%2,%3}, [%4];"
                 : "=r"(r[0]), "=r"(r[1]), "=r"(r[2]), "=r"(r[3]) : "r"(addr));
}
__device__ __forceinline__ void ldsm_x4_t(uint32_t addr, uint32_t* r) {
    asm volatile("ldmatrix.sync.aligned.m8n8.x4.trans.shared.b16 {%0,%1,%2,%3}, [%4];"
                 : "=r"(r[0]), "=r"(r[1]), "=r"(r[2]), "=r"(r[3]) : "r"(addr));
}
__device__ __forceinline__ void mma16816(float* c, const uint32_t* a, const uint32_t* b) {
    asm volatile("mma.sync.aligned.m16n8k16.row.col.f32.f16.f16.f32 "
                 "{%0,%1,%2,%3}, {%4,%5,%6,%7}, {%8,%9}, {%0,%1,%2,%3};"
                 : "+f"(c[0]), "+f"(c[1]), "+f"(c[2]), "+f"(c[3])
                 : "r"(a[0]), "r"(a[1]), "r"(a[2]), "r"(a[3]), "r"(b[0]), "r"(b[1]));
}

// ---- GEMM1 + alpha1 fused: single K=128 stage, dynamic smem ---------------
#define TS 136                                // half stride (17x16B: odd granule)
#define GSM_BYTES (2 * 128 * TS * 2)          // xs + ws = 69632

__global__ void __launch_bounds__(256) gemm1a_kernel(
        const float* __restrict__ x, const float* __restrict__ W,
        const float* __restrict__ a_src, const float* __restrict__ a_dst, int N) {
    extern __shared__ __align__(16) unsigned char smbuf[];
    __half* xs = (__half*)smbuf;                    // [128][TS]
    __half* ws = (__half*)(smbuf + 128 * TS * 2);   // [128][TS]

    int tid  = threadIdx.x;
    int lane = tid & 31;
    int wid  = tid >> 5;
    int row0 = blockIdx.x * 128;
    int R0 = (wid >> 1) * 32;      // warp row base
    int C0 = (wid & 1) * 64;       // warp col base (== head * 64)

#pragma unroll
    for (int j = 0; j < 16; j++) {
        int i = tid + j * 256;
        int r = i >> 5, fc = i & 31;
        int gr = row0 + r; if (gr >= N) gr = N - 1;
        float4 v = *(const float4*)&x[(size_t)gr * 128 + fc * 4];
        __half2* dst = (__half2*)&xs[r * TS + fc * 4];
        dst[0] = __floats2half2_rn(v.x, v.y);
        dst[1] = __floats2half2_rn(v.z, v.w);
    }
#pragma unroll
    for (int j = 0; j < 16; j++) {
        int i = tid + j * 256;
        int r = i >> 5, fc = i & 31;
        float4 v = *(const float4*)&W[(size_t)r * 128 + fc * 4];
        __half2* dst = (__half2*)&ws[r * TS + fc * 4];
        dst[0] = __floats2half2_rn(v.x, v.y);
        dst[1] = __floats2half2_rn(v.z, v.w);
    }
    __syncthreads();

    float acc[2][8][4];
#pragma unroll
    for (int mt = 0; mt < 2; mt++)
#pragma unroll
        for (int nt = 0; nt < 8; nt++)
#pragma unroll
            for (int c = 0; c < 4; c++) acc[mt][nt][c] = 0.f;

    uint32_t xs_base = (uint32_t)__cvta_generic_to_shared(xs);
    uint32_t ws_base = (uint32_t)__cvta_generic_to_shared(ws);

#pragma unroll
    for (int kt = 0; kt < 8; kt++) {
        uint32_t af[2][4];
#pragma unroll
        for (int mt = 0; mt < 2; mt++) {
            uint32_t addr = xs_base + 2 * ((R0 + mt * 16 + (lane & 15)) * TS
                                           + kt * 16 + (lane >> 4) * 8);
            ldsm_x4(addr, af[mt]);
        }
        uint32_t bf[4][4];
#pragma unroll
        for (int np = 0; np < 4; np++) {
            uint32_t addr = ws_base + 2 * ((kt * 16 + (lane & 15)) * TS
                                           + C0 + np * 16 + (lane >> 4) * 8);
            ldsm_x4_t(addr, bf[np]);
        }
#pragma unroll
        for (int mt = 0; mt < 2; mt++)
#pragma unroll
            for (int np = 0; np < 4; np++) {
                mma16816(acc[mt][2 * np],     af[mt], &bf[np][0]);
                mma16816(acc[mt][2 * np + 1], af[mt], &bf[np][2]);
            }
    }

    // ---- alpha epilogue (fp32 from accumulators) ----
    float2 as_l[8], ad_l[8];
#pragma unroll
    for (int nt = 0; nt < 8; nt++) {
        int col = C0 + nt * 8 + (lane & 3) * 2;
        as_l[nt] = *(const float2*)&a_src[col];
        ad_l[nt] = *(const float2*)&a_dst[col];
    }
    int head = wid & 1;
#pragma unroll
    for (int mt = 0; mt < 2; mt++)
#pragma unroll
        for (int rh = 0; rh < 2; rh++) {
            float ps = 0.f, pd = 0.f;
#pragma unroll
            for (int nt = 0; nt < 8; nt++) {
                float v0 = acc[mt][nt][2 * rh], v1 = acc[mt][nt][2 * rh + 1];
                ps += v0 * as_l[nt].x + v1 * as_l[nt].y;
                pd += v0 * ad_l[nt].x + v1 * ad_l[nt].y;
            }
            ps += __shfl_xor_sync(0xffffffffu, ps, 1);
            pd += __shfl_xor_sync(0xffffffffu, pd, 1);
            ps += __shfl_xor_sync(0xffffffffu, ps, 2);
            pd += __shfl_xor_sync(0xffffffffu, pd, 2);
            if ((lane & 3) == 0) {
                int row = row0 + R0 + mt * 16 + rh * 8 + (lane >> 2);
                if (row < N) {
                    g_as1[2 * row + head] = ps;
                    g_ad1[2 * row + head] = pd;
                }
            }
        }

    // ---- direct fp16 stores ----
#pragma unroll
    for (int mt = 0; mt < 2; mt++)
#pragma unroll
        for (int nt = 0; nt < 8; nt++) {
            int r  = row0 + R0 + mt * 16 + (lane >> 2);
            int cc = C0 + nt * 8 + (lane & 3) * 2;
            if (r < N)
                *(__half2*)&g_xw1h[(size_t)r * 128 + cc] =
                    __floats2half2_rn(acc[mt][nt][0], acc[mt][nt][1]);
            if (r + 8 < N)
                *(__half2*)&g_xw1h[(size_t)(r + 8) * 128 + cc] =
                    __floats2half2_rn(acc[mt][nt][2], acc[mt][nt][3]);
        }
}

// ---- Layer1 aggregation: 2 warps/node, R12 gather pattern, precomputed w --
__global__ void __launch_bounds__(256) agg1_kernel(
        const float* __restrict__ b1, const float* __restrict__ W2,
        const float* __restrict__ a_src2, const float* __restrict__ a_dst2, int N) {
    __shared__ float p_sh[8][2];
    int wip  = threadIdx.x >> 5;
    int lane = threadIdx.x & 31;
    int d    = blockIdx.x * 4 + (wip >> 1);
    int head = wip & 1;
    bool valid = d < N;

    if (valid) {
        int rbase = d << 7;
        int cntr  = g_cnt[d]; if (cntr > SLOTS) cntr = SLOTS;
        int pad   = (cntr + 7) & ~7;
        int grp = lane >> 4;
        int cq  = (lane & 15) * 4;
        const __half* bx = g_xw1h + head * 64 + cq;
        const float* wv = head ? g_w1 : g_w0;
        float4 accA = make_float4(0.f, 0.f, 0.f, 0.f);
        float4 accB = make_float4(0.f, 0.f, 0.f, 0.f);
        float4 ds4  = make_float4(0.f, 0.f, 0.f, 0.f);

        for (int g = 0; g < pad; g += 8) {
            int4   sa = *(const int4*)&g_colf[rbase + g];       // broadcast
            int4   sb = *(const int4*)&g_colf[rbase + g + 4];
            float4 wa = *(const float4*)&wv[rbase + g];         // broadcast
            float4 wb = *(const float4*)&wv[rbase + g + 4];
            ds4.x += wa.x + wb.x; ds4.y += wa.y + wb.y;
            ds4.z += wa.z + wb.z; ds4.w += wa.w + wb.w;
            int   sA = grp ? sa.y : sa.x;
            int   sB = grp ? sa.w : sa.z;
            int   sC = grp ? sb.y : sb.x;
            int   sD = grp ? sb.w : sb.z;
            float wA = grp ? wa.y : wa.x;
            float wB = grp ? wa.w : wa.z;
            float wC = grp ? wb.y : wb.x;
            float wD = grp ? wb.w : wb.z;
            uint2 rA = *(const uint2*)&bx[(size_t)sA * 128];
            uint2 rB = *(const uint2*)&bx[(size_t)sB * 128];
            uint2 rC = *(const uint2*)&bx[(size_t)sC * 128];
            uint2 rD = *(const uint2*)&bx[(size_t)sD * 128];
            float2 vA0 = __half22float2(*(__half2*)&rA.x);
            float2 vA1 = __half22float2(*(__half2*)&rA.y);
            float2 vB0 = __half22float2(*(__half2*)&rB.x);
            float2 vB1 = __half22float2(*(__half2*)&rB.y);
            float2 vC0 = __half22float2(*(__half2*)&rC.x);
            float2 vC1 = __half22float2(*(__half2*)&rC.y);
            float2 vD0 = __half22float2(*(__half2*)&rD.x);
            float2 vD1 = __half22float2(*(__half2*)&rD.y);
            accA.x += wA * vA0.x; accA.y += wA * vA0.y;
            accA.z += wA * vA1.x; accA.w += wA * vA1.y;
            accB.x += wB * vB0.x; accB.y += wB * vB0.y;
            accB.z += wB * vB1.x; accB.w += wB * vB1.y;
            accA.x += wC * vC0.x; accA.y += wC * vC0.y;
            accA.z += wC * vC1.x; accA.w += wC * vC1.y;
            accB.x += wD * vD0.x; accB.y += wD * vD0.y;
            accB.z += wD * vD1.x; accB.w += wD * vD1.y;
        }
        // merge the two 16-lane groups
        accA.x += accB.x; accA.y += accB.y; accA.z += accB.z; accA.w += accB.w;
        accA.x += __shfl_xor_sync(0xffffffffu, accA.x, 16);
        accA.y += __shfl_xor_sync(0xffffffffu, accA.y, 16);
        accA.z += __shfl_xor_sync(0xffffffffu, accA.z, 16);
        accA.w += __shfl_xor_sync(0xffffffffu, accA.w, 16);
        // ds is uniform across lanes (every lane summed all broadcast weights)
        float ds = ds4.x + ds4.y + ds4.z + ds4.w;
        float inv = 1.f / (ds + 1e-16f);
        int cg = head * 64 + cq;
        float4 bb = *(const float4*)&b1[cg];
        float hx = elu(accA.x * inv + bb.x);
        float hy = elu(accA.y * inv + bb.y);
        float hz = elu(accA.z * inv + bb.z);
        float hw = elu(accA.w * inv + bb.w);
        // fused layer2 transform partials over this head's channels
        float p0 = hx * W2[2*cg]   + hy * W2[2*(cg+1)]   + hz * W2[2*(cg+2)]   + hw * W2[2*(cg+3)];
        float p1 = hx * W2[2*cg+1] + hy * W2[2*(cg+1)+1] + hz * W2[2*(cg+2)+1] + hw * W2[2*(cg+3)+1];
#pragma unroll
        for (int o = 1; o < 16; o <<= 1) {
            p0 += __shfl_xor_sync(0xffffffffu, p0, o);
            p1 += __shfl_xor_sync(0xffffffffu, p1, o);
        }
        if (lane == 0) { p_sh[wip][0] = p0; p_sh[wip][1] = p1; }
    }
    __syncthreads();
    if (valid && head == 0 && lane == 0) {
        float q0 = p_sh[wip][0] + p_sh[wip + 1][0];
        float q1 = p_sh[wip][1] + p_sh[wip + 1][1];
        float4 nv;
        nv.x = q0; nv.y = q1;
        nv.z = q0 * a_src2[0] + q1 * a_src2[1];
        nv.w = q0 * a_dst2[0] + q1 * a_dst2[1];
        g_n2[d] = nv;
    }
}

// ---- Layer2 aggregation: warp per dst node, single pass -------------------
__global__ void agg2_kernel(const float* __restrict__ b2, float* __restrict__ out, int N) {
    int warp = (blockIdx.x * blockDim.x + threadIdx.x) >> 5;
    int lane = threadIdx.x & 31;
    if (warp >= N) return;
    int d = warp;
    int rbase = d << 7;
    int cntr  = g_cnt[d]; if (cntr > SLOTS) cntr = SLOTS;
    float adv = g_n2[d].w;
    float a0 = 0.f, a1 = 0.f, ds = 0.f;
    for (int i = lane; i < cntr; i += 32) {
        float4 nv = g_n2[g_colf[rbase + i]];
        float w = __expf(lrelu(nv.z + adv));
        ds += w; a0 += w * nv.x; a1 += w * nv.y;
    }
#pragma unroll
    for (int o = 16; o; o >>= 1) {
        a0 += __shfl_xor_sync(0xffffffffu, a0, o);
        a1 += __shfl_xor_sync(0xffffffffu, a1, o);
        ds += __shfl_xor_sync(0xffffffffu, ds, o);
    }
    if (lane == 0) {
        float inv = 1.f / (ds + 1e-16f);
        out[2 * d]     = a0 * inv + b2[0];
        out[2 * d + 1] = a1 * inv + b2[1];
    }
}

// ---------------------------------------------------------------------------
extern "C" void kernel_launch(void* const* d_in, const int* in_sizes, int n_in,
                              void* d_out, int out_size) {
    const float* x    = (const float*)d_in[0];
    const void*  eidx = d_in[1];
    const float* W1   = (const float*)d_in[2];
    const float* as1  = (const float*)d_in[3];
    const float* ad1  = (const float*)d_in[4];
    const float* b1   = (const float*)d_in[5];
    const float* W2   = (const float*)d_in[6];
    const float* as2  = (const float*)d_in[7];
    const float* ad2  = (const float*)d_in[8];
    const float* b2   = (const float*)d_in[9];

    int N = in_sizes[0] / 128;
    int E = in_sizes[1] / 2;
    int nt4 = (E + 3) / 4;
    int ntw = N * 32;

    static cudaStream_t s_side = nullptr;
    static cudaEvent_t  ev_fork = nullptr, ev_join = nullptr;
    if (!s_side) {   // created on the uncaptured correctness call, reused after
        cudaStreamCreateWithFlags(&s_side, cudaStreamNonBlocking);
        cudaEventCreateWithFlags(&ev_fork, cudaEventDisableTiming);
        cudaEventCreateWithFlags(&ev_join, cudaEventDisableTiming);
        cudaFuncSetAttribute(gemm1a_kernel,
                             cudaFuncAttributeMaxDynamicSharedMemorySize, GSM_BYTES);
    }

    // main: init, then fork fill to side stream; GEMM overlaps it.
    init_kernel<<<(N + 255) / 256, 256>>>((const unsigned int*)eidx, N);   // 0
    cudaEventRecord(ev_fork, 0);
    cudaStreamWaitEvent(s_side, ev_fork, 0);

    fill_kernel<<<(nt4 + 255) / 256, 256, 0, s_side>>>(eidx, E);           // 1
    cudaEventRecord(ev_join, s_side);

    gemm1a_kernel<<<(N + 127) / 128, 256, GSM_BYTES>>>(x, W1, as1, ad1, N);// 2

    cudaStreamWaitEvent(0, ev_join, 0);
    wgt_kernel<<<(ntw + 255) / 256, 256>>>(N);                             // 3
    agg1_kernel<<<(N + 3) / 4, 256>>>(b1, W2, as2, ad2, N);                // 4
    agg2_kernel<<<(N + 7) / 8, 256>>>(b2, (float*)d_out, N);               // 5
}

// round 17
// speedup vs baseline: 1.2346x; 1.2330x over previous
#include <cuda_runtime.h>
#include <cuda_fp16.h>
#include <math.h>
#include <stdint.h>

// ---------------------------------------------------------------------------
// ImbalancedGAT R17 (third submission of the R15 change; R15/R16 both hit
// broker-level "container failed twice" — kernel never executed):
// exact R12 (best measured: 125.5us) + occupancy nudge on agg1
// (__launch_bounds__(256, 7): 40->36 regs, 6->7 blocks/SM).
// ---------------------------------------------------------------------------

#define MAXN 65536
#define SLOTS 128

__device__ __half  g_xw1h[MAXN * 128]; // layer1 transformed features (fp16)
__device__ float   g_as1[MAXN * 2];    // alpha_src layer1 (per head)
__device__ float   g_ad1[MAXN * 2];    // alpha_dst layer1
__device__ float4  g_n2[MAXN];         // {xw2_0, xw2_1, as2, ad2}
__device__ int     g_cnt[MAXN];        // row length (starts at 1: self loop)
__device__ int     g_colf[MAXN * SLOTS]; // fixed-slot adjacency
__device__ int     g_is64;

__device__ __forceinline__ float lrelu(float x) { return x > 0.f ? x : 0.2f * x; }
__device__ __forceinline__ float elu(float x)   { return x > 0.f ? x : (expf(x) - 1.f); }

// ---- init: cnt=1, self loop at slot 0, dtype detection --------------------
__global__ void init_kernel(const unsigned int* ew, int n) {
    int i = blockIdx.x * blockDim.x + threadIdx.x;
    if (i < n) {
        g_cnt[i] = 1;
        g_colf[i << 7] = i;   // self loop at row head
    }
    if (blockIdx.x == 0 && threadIdx.x < 32) {
        int lane = threadIdx.x;
        int nz = 0;
        for (int k = lane; k < 1024; k += 32) nz += (ew[2 * k + 1] != 0u);
        for (int o = 16; o; o >>= 1) nz += __shfl_xor_sync(0xffffffffu, nz, o);
        if (lane == 0) g_is64 = (nz == 0);  // all-zero high words => int64
    }
}

// ---- fill: 4 edges/thread, independent atomic chains ----------------------
__global__ void fill_kernel(const void* e, int E) {
    int t = blockIdx.x * blockDim.x + threadIdx.x;
    int base = t * 4;
    if (base >= E) return;
    int n = E - base; if (n > 4) n = 4;
    int s[4], d[4];
    if (g_is64) {
        const long long* ps = (const long long*)e + base;
        const long long* pd = (const long long*)e + E + base;
        if (n == 4) {
            longlong2 a = *(const longlong2*)ps, b = *(const longlong2*)(ps + 2);
            longlong2 c = *(const longlong2*)pd, f = *(const longlong2*)(pd + 2);
            s[0]=(int)a.x; s[1]=(int)a.y; s[2]=(int)b.x; s[3]=(int)b.y;
            d[0]=(int)c.x; d[1]=(int)c.y; d[2]=(int)f.x; d[3]=(int)f.y;
        } else {
            for (int i = 0; i < n; i++) { s[i]=(int)ps[i]; d[i]=(int)pd[i]; }
        }
    } else {
        const int* ps = (const int*)e + base;
        const int* pd = (const int*)e + E + base;
        if (n == 4) {
            int4 sv = *(const int4*)ps, dv = *(const int4*)pd;
            s[0]=sv.x; s[1]=sv.y; s[2]=sv.z; s[3]=sv.w;
            d[0]=dv.x; d[1]=dv.y; d[2]=dv.z; d[3]=dv.w;
        } else {
            for (int i = 0; i < n; i++) { s[i]=ps[i]; d[i]=pd[i]; }
        }
    }
#pragma unroll
    for (int i = 0; i < 4; i++) {
        if (i < n) {
            int pos = atomicAdd(&g_cnt[d[i]], 1);
            if (pos < SLOTS) g_colf[(d[i] << 7) + pos] = s[i];
        }
    }
}

// ---- mma helpers ----------------------------------------------------------
__device__ __forceinline__ void ldsm_x4(uint32_t addr, uint32_t* r) {
    asm volatile("ldmatrix.sync.aligned.m8n8.x4.shared.b16 {%0,%1,%2,%3}, [%4];"
                 : "=r"(r[0]), "=r"(r[1]), "=r"(r[2]), "=r"(r[3]) : "r"(addr));
}
__device__ __forceinline__ void ldsm_x4_t(uint32_t addr, uint32_t* r) {
    asm volatile("ldmatrix.sync.aligned.m8n8.x4.trans.shared.b16 {%0,%1,%2,%3}, [%4];"
                 : "=r"(r[0]), "=r"(r[1]), "=r"(r[2]), "=r"(r[3]) : "r"(addr));
}
__device__ __forceinline__ void mma16816(float* c, const uint32_t* a, const uint32_t* b) {
    asm volatile("mma.sync.aligned.m16n8k16.row.col.f32.f16.f16.f32 "
                 "{%0,%1,%2,%3}, {%4,%5,%6,%7}, {%8,%9}, {%0,%1,%2,%3};"
                 : "+f"(c[0]), "+f"(c[1]), "+f"(c[2]), "+f"(c[3])
                 : "r"(a[0]), "r"(a[1]), "r"(a[2]), "r"(a[3]), "r"(b[0]), "r"(b[1]));
}

// ---- GEMM1 + alpha1 fused: single K=128 stage, dynamic smem ---------------
#define TS 136                                // half stride (17x16B: odd granule)
#define GSM_BYTES (2 * 128 * TS * 2)          // xs + ws = 69632

__global__ void __launch_bounds__(256) gemm1a_kernel(
        const float* __restrict__ x, const float* __restrict__ W,
        const float* __restrict__ a_src, const float* __restrict__ a_dst, int N) {
    extern __shared__ __align__(16) unsigned char smbuf[];
    __half* xs = (__half*)smbuf;                    // [128][TS]
    __half* ws = (__half*)(smbuf + 128 * TS * 2);   // [128][TS]

    int tid  = threadIdx.x;
    int lane = tid & 31;
    int wid  = tid >> 5;
    int row0 = blockIdx.x * 128;
    int R0 = (wid >> 1) * 32;      // warp row base
    int C0 = (wid & 1) * 64;       // warp col base (== head * 64)

#pragma unroll
    for (int j = 0; j < 16; j++) {
        int i = tid + j * 256;
        int r = i >> 5, fc = i & 31;
        int gr = row0 + r; if (gr >= N) gr = N - 1;
        float4 v = *(const float4*)&x[(size_t)gr * 128 + fc * 4];
        __half2* dst = (__half2*)&xs[r * TS + fc * 4];
        dst[0] = __floats2half2_rn(v.x, v.y);
        dst[1] = __floats2half2_rn(v.z, v.w);
    }
#pragma unroll
    for (int j = 0; j < 16; j++) {
        int i = tid + j * 256;
        int r = i >> 5, fc = i & 31;
        float4 v = *(const float4*)&W[(size_t)r * 128 + fc * 4];
        __half2* dst = (__half2*)&ws[r * TS + fc * 4];
        dst[0] = __floats2half2_rn(v.x, v.y);
        dst[1] = __floats2half2_rn(v.z, v.w);
    }
    __syncthreads();

    float acc[2][8][4];
#pragma unroll
    for (int mt = 0; mt < 2; mt++)
#pragma unroll
        for (int nt = 0; nt < 8; nt++)
#pragma unroll
            for (int c = 0; c < 4; c++) acc[mt][nt][c] = 0.f;

    uint32_t xs_base = (uint32_t)__cvta_generic_to_shared(xs);
    uint32_t ws_base = (uint32_t)__cvta_generic_to_shared(ws);

#pragma unroll
    for (int kt = 0; kt < 8; kt++) {
        uint32_t af[2][4];
#pragma unroll
        for (int mt = 0; mt < 2; mt++) {
            uint32_t addr = xs_base + 2 * ((R0 + mt * 16 + (lane & 15)) * TS
                                           + kt * 16 + (lane >> 4) * 8);
            ldsm_x4(addr, af[mt]);
        }
        uint32_t bf[4][4];
#pragma unroll
        for (int np = 0; np < 4; np++) {
            uint32_t addr = ws_base + 2 * ((kt * 16 + (lane & 15)) * TS
                                           + C0 + np * 16 + (lane >> 4) * 8);
            ldsm_x4_t(addr, bf[np]);
        }
#pragma unroll
        for (int mt = 0; mt < 2; mt++)
#pragma unroll
            for (int np = 0; np < 4; np++) {
                mma16816(acc[mt][2 * np],     af[mt], &bf[np][0]);
                mma16816(acc[mt][2 * np + 1], af[mt], &bf[np][2]);
            }
    }

    // ---- alpha epilogue (fp32 from accumulators) ----
    float2 as_l[8], ad_l[8];
#pragma unroll
    for (int nt = 0; nt < 8; nt++) {
        int col = C0 + nt * 8 + (lane & 3) * 2;
        as_l[nt] = *(const float2*)&a_src[col];
        ad_l[nt] = *(const float2*)&a_dst[col];
    }
    int head = wid & 1;
#pragma unroll
    for (int mt = 0; mt < 2; mt++)
#pragma unroll
        for (int rh = 0; rh < 2; rh++) {
            float ps = 0.f, pd = 0.f;
#pragma unroll
            for (int nt = 0; nt < 8; nt++) {
                float v0 = acc[mt][nt][2 * rh], v1 = acc[mt][nt][2 * rh + 1];
                ps += v0 * as_l[nt].x + v1 * as_l[nt].y;
                pd += v0 * ad_l[nt].x + v1 * ad_l[nt].y;
            }
            ps += __shfl_xor_sync(0xffffffffu, ps, 1);
            pd += __shfl_xor_sync(0xffffffffu, pd, 1);
            ps += __shfl_xor_sync(0xffffffffu, ps, 2);
            pd += __shfl_xor_sync(0xffffffffu, pd, 2);
            if ((lane & 3) == 0) {
                int row = row0 + R0 + mt * 16 + rh * 8 + (lane >> 2);
                if (row < N) {
                    g_as1[2 * row + head] = ps;
                    g_ad1[2 * row + head] = pd;
                }
            }
        }

    // ---- direct fp16 stores ----
#pragma unroll
    for (int mt = 0; mt < 2; mt++)
#pragma unroll
        for (int nt = 0; nt < 8; nt++) {
            int r  = row0 + R0 + mt * 16 + (lane >> 2);
            int cc = C0 + nt * 8 + (lane & 3) * 2;
            if (r < N)
                *(__half2*)&g_xw1h[(size_t)r * 128 + cc] =
                    __floats2half2_rn(acc[mt][nt][0], acc[mt][nt][1]);
            if (r + 8 < N)
                *(__half2*)&g_xw1h[(size_t)(r + 8) * 128 + cc] =
                    __floats2half2_rn(acc[mt][nt][2], acc[mt][nt][3]);
        }
}

// ---- Layer1 aggregation: 2 warps/node, R12 smem-staged gather pattern -----
__global__ void __launch_bounds__(256, 7) agg1_kernel(
        const float* __restrict__ b1, const float* __restrict__ W2,
        const float* __restrict__ a_src2, const float* __restrict__ a_dst2, int N) {
    __shared__ int   s_sh[8][64];
    __shared__ float w_sh[8][64];
    __shared__ float p_sh[8][2];
    int wip  = threadIdx.x >> 5;
    int lane = threadIdx.x & 31;
    int d    = blockIdx.x * 4 + (wip >> 1);
    int head = wip & 1;
    bool valid = d < N;

    if (valid) {
        int rbase = d << 7;
        int cntr  = g_cnt[d]; if (cntr > SLOTS) cntr = SLOTS;
        float adv = g_ad1[2 * d + head];
        int grp = lane >> 4;
        int cq  = (lane & 15) * 4;
        const __half* bx = g_xw1h + head * 64 + cq;
        float4 accA = make_float4(0.f, 0.f, 0.f, 0.f);
        float4 accB = make_float4(0.f, 0.f, 0.f, 0.f);
        float ds = 0.f;
        int*   ss = s_sh[wip];
        float* ws = w_sh[wip];

        for (int b0 = 0; b0 < cntr; b0 += 64) {
            int i0 = b0 + lane, i1 = b0 + 32 + lane;
            int s0 = d, s1 = d; float w0 = 0.f, w1 = 0.f;
            if (i0 < cntr) {
                s0 = g_colf[rbase + i0];
                w0 = __expf(lrelu(g_as1[2 * s0 + head] + adv));  // no max: bounded
                ds += w0;
            }
            if (i1 < cntr) {
                s1 = g_colf[rbase + i1];
                w1 = __expf(lrelu(g_as1[2 * s1 + head] + adv));
                ds += w1;
            }
            __syncwarp();
            ss[lane] = s0; ws[lane] = w0;
            ss[32 + lane] = s1; ws[32 + lane] = w1;
            __syncwarp();
            int cnt = cntr - b0; if (cnt > 64) cnt = 64;
            cnt = (cnt + 7) & ~7;                  // pad: w=0 entries no-op
            for (int g = 0; g < cnt; g += 8) {
                int4   sa = *(const int4*)&ss[g];
                int4   sb = *(const int4*)&ss[g + 4];
                float4 wa = *(const float4*)&ws[g];
                float4 wb = *(const float4*)&ws[g + 4];
                int   sA = grp ? sa.y : sa.x;
                int   sB = grp ? sa.w : sa.z;
                int   sC = grp ? sb.y : sb.x;
                int   sD = grp ? sb.w : sb.z;
                float wA = grp ? wa.y : wa.x;
                float wB = grp ? wa.w : wa.z;
                float wC = grp ? wb.y : wb.x;
                float wD = grp ? wb.w : wb.z;
                uint2 rA = *(const uint2*)&bx[(size_t)sA * 128];
                uint2 rB = *(const uint2*)&bx[(size_t)sB * 128];
                uint2 rC = *(const uint2*)&bx[(size_t)sC * 128];
                uint2 rD = *(const uint2*)&bx[(size_t)sD * 128];
                float2 vA0 = __half22float2(*(__half2*)&rA.x);
                float2 vA1 = __half22float2(*(__half2*)&rA.y);
                float2 vB0 = __half22float2(*(__half2*)&rB.x);
                float2 vB1 = __half22float2(*(__half2*)&rB.y);
                float2 vC0 = __half22float2(*(__half2*)&rC.x);
                float2 vC1 = __half22float2(*(__half2*)&rC.y);
                float2 vD0 = __half22float2(*(__half2*)&rD.x);
                float2 vD1 = __half22float2(*(__half2*)&rD.y);
                accA.x += wA * vA0.x; accA.y += wA * vA0.y;
                accA.z += wA * vA1.x; accA.w += wA * vA1.y;
                accB.x += wB * vB0.x; accB.y += wB * vB0.y;
                accB.z += wB * vB1.x; accB.w += wB * vB1.y;
                accA.x += wC * vC0.x; accA.y += wC * vC0.y;
                accA.z += wC * vC1.x; accA.w += wC * vC1.y;
                accB.x += wD * vD0.x; accB.y += wD * vD0.y;
                accB.z += wD * vD1.x; accB.w += wD * vD1.y;
            }
        }
        // merge the two 16-lane groups
        accA.x += accB.x; accA.y += accB.y; accA.z += accB.z; accA.w += accB.w;
        accA.x += __shfl_xor_sync(0xffffffffu, accA.x, 16);
        accA.y += __shfl_xor_sync(0xffffffffu, accA.y, 16);
        accA.z += __shfl_xor_sync(0xffffffffu, accA.z, 16);
        accA.w += __shfl_xor_sync(0xffffffffu, accA.w, 16);
#pragma unroll
        for (int o = 16; o; o >>= 1)
            ds += __shfl_xor_sync(0xffffffffu, ds, o);
        float inv = 1.f / (ds + 1e-16f);
        int cg = head * 64 + cq;
        float4 bb = *(const float4*)&b1[cg];
        float hx = elu(accA.x * inv + bb.x);
        float hy = elu(accA.y * inv + bb.y);
        float hz = elu(accA.z * inv + bb.z);
        float hw = elu(accA.w * inv + bb.w);
        // fused layer2 transform partials over this head's channels
        float p0 = hx * W2[2*cg]   + hy * W2[2*(cg+1)]   + hz * W2[2*(cg+2)]   + hw * W2[2*(cg+3)];
        float p1 = hx * W2[2*cg+1] + hy * W2[2*(cg+1)+1] + hz * W2[2*(cg+2)+1] + hw * W2[2*(cg+3)+1];
#pragma unroll
        for (int o = 1; o < 16; o <<= 1) {
            p0 += __shfl_xor_sync(0xffffffffu, p0, o);
            p1 += __shfl_xor_sync(0xffffffffu, p1, o);
        }
        if (lane == 0) { p_sh[wip][0] = p0; p_sh[wip][1] = p1; }
    }
    __syncthreads();
    if (valid && head == 0 && lane == 0) {
        float q0 = p_sh[wip][0] + p_sh[wip + 1][0];
        float q1 = p_sh[wip][1] + p_sh[wip + 1][1];
        float4 nv;
        nv.x = q0; nv.y = q1;
        nv.z = q0 * a_src2[0] + q1 * a_src2[1];
        nv.w = q0 * a_dst2[0] + q1 * a_dst2[1];
        g_n2[d] = nv;
    }
}

// ---- Layer2 aggregation: warp per dst node, single pass -------------------
__global__ void agg2_kernel(const float* __restrict__ b2, float* __restrict__ out, int N) {
    int warp = (blockIdx.x * blockDim.x + threadIdx.x) >> 5;
    int lane = threadIdx.x & 31;
    if (warp >= N) return;
    int d = warp;
    int rbase = d << 7;
    int cntr  = g_cnt[d]; if (cntr > SLOTS) cntr = SLOTS;
    float adv = g_n2[d].w;
    float a0 = 0.f, a1 = 0.f, ds = 0.f;
    for (int i = lane; i < cntr; i += 32) {
        float4 nv = g_n2[g_colf[rbase + i]];
        float w = __expf(lrelu(nv.z + adv));
        ds += w; a0 += w * nv.x; a1 += w * nv.y;
    }
#pragma unroll
    for (int o = 16; o; o >>= 1) {
        a0 += __shfl_xor_sync(0xffffffffu, a0, o);
        a1 += __shfl_xor_sync(0xffffffffu, a1, o);
        ds += __shfl_xor_sync(0xffffffffu, ds, o);
    }
    if (lane == 0) {
        float inv = 1.f / (ds + 1e-16f);
        out[2 * d]     = a0 * inv + b2[0];
        out[2 * d + 1] = a1 * inv + b2[1];
    }
}

// ---------------------------------------------------------------------------
extern "C" void kernel_launch(void* const* d_in, const int* in_sizes, int n_in,
                              void* d_out, int out_size) {
    const float* x    = (const float*)d_in[0];
    const void*  eidx = d_in[1];
    const float* W1   = (const float*)d_in[2];
    const float* as1  = (const float*)d_in[3];
    const float* ad1  = (const float*)d_in[4];
    const float* b1   = (const float*)d_in[5];
    const float* W2   = (const float*)d_in[6];
    const float* as2  = (const float*)d_in[7];
    const float* ad2  = (const float*)d_in[8];
    const float* b2   = (const float*)d_in[9];

    int N = in_sizes[0] / 128;
    int E = in_sizes[1] / 2;
    int nt4 = (E + 3) / 4;

    static cudaStream_t s_side = nullptr;
    static cudaEvent_t  ev_fork = nullptr, ev_join = nullptr;
    if (!s_side) {   // created on the uncaptured correctness call, reused after
        cudaStreamCreateWithFlags(&s_side, cudaStreamNonBlocking);
        cudaEventCreateWithFlags(&ev_fork, cudaEventDisableTiming);
        cudaEventCreateWithFlags(&ev_join, cudaEventDisableTiming);
        cudaFuncSetAttribute(gemm1a_kernel,
                             cudaFuncAttributeMaxDynamicSharedMemorySize, GSM_BYTES);
    }

    // main: init, then fork fill to side stream; GEMM overlaps it.
    init_kernel<<<(N + 255) / 256, 256>>>((const unsigned int*)eidx, N);   // 0
    cudaEventRecord(ev_fork, 0);
    cudaStreamWaitEvent(s_side, ev_fork, 0);

    fill_kernel<<<(nt4 + 255) / 256, 256, 0, s_side>>>(eidx, E);           // 1
    cudaEventRecord(ev_join, s_side);

    gemm1a_kernel<<<(N + 127) / 128, 256, GSM_BYTES>>>(x, W1, as1, ad1, N);// 2

    cudaStreamWaitEvent(0, ev_join, 0);
    agg1_kernel<<<(N + 3) / 4, 256>>>(b1, W2, as2, ad2, N);                // 3 <- profiled
    agg2_kernel<<<(N + 7) / 8, 256>>>(b2, (float*)d_out, N);               // 4
}